// round 16
// baseline (speedup 1.0000x reference)
#include <cuda_runtime.h>
#include <float.h>

// Shapes (fixed by the problem): B=32, S=4096, H=1024, K=2
#define B_ 32
#define S_ 4096
#define H_ 1024
#define K_ 2

#define LANES   32                 // feature lanes per block (float4 each) = 1 warp
#define GROUPS  16                 // row groups per block (1 warp each)
#define THREADS (LANES*GROUPS)     // 512
#define CHUNK   (LANES*4)          // 128 features per block
#define CHUNKS  (H_/CHUNK)         // 8

__device__ __forceinline__ float4 f4max(float4 a, float4 b) {
    float4 r;
    r.x = fmaxf(a.x, b.x);
    r.y = fmaxf(a.y, b.y);
    r.z = fmaxf(a.z, b.z);
    r.w = fmaxf(a.w, b.w);
    return r;
}

__global__ void __launch_bounds__(THREADS)
span_max_kernel(const float* __restrict__ hs,   // [B, S, H]
                const int* __restrict__ st,     // [B, K] (int32)
                const int* __restrict__ en,     // [B, K]
                const float* __restrict__ me,   // [K, H]
                float* __restrict__ out)        // [B, K*H]
{
    __shared__ float4 part[GROUPS][LANES];

    const int blk   = blockIdx.x;
    const int chunk = blk % CHUNKS;
    const int bk    = blk / CHUNKS;
    const int b     = bk / K_;
    const int k     = bk % K_;

    const int lane = threadIdx.x & (LANES - 1);  // lane within warp
    const int g    = threadIdx.x / LANES;        // warp id = row group

    const int f = chunk * CHUNK + lane * 4;      // feature offset

    const int s_raw = __ldg(&st[b * K_ + k]);
    const int e_raw = __ldg(&en[b * K_ + k]);

    float* op = out + (size_t)b * (K_ * H_) + (size_t)k * H_ + f;

    if (s_raw < 0 || e_raw < 0) {
        // missing: copy missing_embeddings[k]; uniform branch, all threads
        // return without touching the named barrier.
        if (g == 0) {
            float4 v = *reinterpret_cast<const float4*>(me + (size_t)k * H_ + f);
            *reinterpret_cast<float4*>(op) = v;
        }
        return;
    }

    // defensive clamps: keep all generated row indices inside [0, S) and the
    // span within the 64 covered rows (reference guarantees length < 64, so
    // this never changes the result; it only makes any input safe).
    const int s  = s_raw < S_ ? s_raw : S_;
    int       e  = e_raw < S_ ? e_raw : S_;
    const int em = s + 4 * GROUPS;               // s + 64
    e = e < em ? e : em;

    const float* base = hs + ((size_t)b * S_) * H_ + f;

    const float4 NEG = make_float4(-FLT_MAX, -FLT_MAX, -FLT_MAX, -FLT_MAX);

    // rows covered: s+g+16j, j in [0,4) => s..s+63. 4 independent PREDICATED
    // loads per thread (no duplicate traffic), back-to-back: one latency wait.
    const int r0 = s + g;
    const int r1 = r0 + GROUPS;
    const int r2 = r0 + 2 * GROUPS;
    const int r3 = r0 + 3 * GROUPS;

    float4 a0 = (r0 < e) ? *reinterpret_cast<const float4*>(base + (size_t)r0 * H_) : NEG;
    float4 a1 = (r1 < e) ? *reinterpret_cast<const float4*>(base + (size_t)r1 * H_) : NEG;
    float4 a2 = (r2 < e) ? *reinterpret_cast<const float4*>(base + (size_t)r2 * H_) : NEG;
    float4 a3 = (r3 < e) ? *reinterpret_cast<const float4*>(base + (size_t)r3 * H_) : NEG;

    part[g][lane] = f4max(f4max(a0, a1), f4max(a2, a3));

    // Asymmetric barrier: warps 1..15 arrive and EXIT immediately (SM frees
    // them right after their loads land); only warp 0 blocks, reduces, stores.
    if (g != 0) {
        asm volatile("bar.arrive 1, %0;" :: "r"(THREADS) : "memory");
        return;
    }
    asm volatile("bar.sync 1, %0;" :: "r"(THREADS) : "memory");

    // 15 independent LDS.128 + fmax tree (single warp)
    float4 acc = part[0][lane];
    #pragma unroll
    for (int i = 1; i < GROUPS; i++)
        acc = f4max(acc, part[i][lane]);
    *reinterpret_cast<float4*>(op) = acc;
}

extern "C" void kernel_launch(void* const* d_in, const int* in_sizes, int n_in,
                              void* d_out, int out_size) {
    const float* hs  = (const float*)d_in[0];
    const int*   st  = (const int*)d_in[1];
    const int*   en  = (const int*)d_in[2];
    const float* me  = (const float*)d_in[3];
    float*       out = (float*)d_out;

    dim3 grid(B_ * K_ * CHUNKS);   // 512 blocks x 512 threads
    span_max_kernel<<<grid, THREADS>>>(hs, st, en, me, out);
}

// round 17
// speedup vs baseline: 1.0386x; 1.0386x over previous
#include <cuda_runtime.h>
#include <float.h>

// Shapes (fixed by the problem): B=32, S=4096, H=1024, K=2
#define B_ 32
#define S_ 4096
#define H_ 1024
#define K_ 2

#define LANES   32                 // feature lanes per block (float4 each) = 1 warp
#define GROUPS  16                 // row groups per block (1 warp each)
#define THREADS (LANES*GROUPS)     // 512
#define CHUNK   (LANES*4)          // 128 features per block
#define CHUNKS  (H_/CHUNK)         // 8

__device__ __forceinline__ float4 f4max(float4 a, float4 b) {
    float4 r;
    r.x = fmaxf(a.x, b.x);
    r.y = fmaxf(a.y, b.y);
    r.z = fmaxf(a.z, b.z);
    r.w = fmaxf(a.w, b.w);
    return r;
}

__global__ void __launch_bounds__(THREADS)
span_max_kernel(const float* __restrict__ hs,   // [B, S, H]
                const int* __restrict__ st,     // [B, K] (int32)
                const int* __restrict__ en,     // [B, K]
                const float* __restrict__ me,   // [K, H]
                float* __restrict__ out)        // [B, K*H]
{
    __shared__ float4 part[GROUPS][LANES];

    const int blk   = blockIdx.x;
    const int chunk = blk % CHUNKS;
    const int bk    = blk / CHUNKS;
    const int b     = bk / K_;
    const int k     = bk % K_;

    const int lane = threadIdx.x & (LANES - 1);  // lane within warp
    const int g    = threadIdx.x / LANES;        // warp id = row group

    const int f = chunk * CHUNK + lane * 4;      // feature offset

    const int s_raw = __ldg(&st[b * K_ + k]);
    const int e_raw = __ldg(&en[b * K_ + k]);

    float* op = out + (size_t)b * (K_ * H_) + (size_t)k * H_ + f;

    if (s_raw < 0 || e_raw < 0) {
        // missing: copy missing_embeddings[k]; uniform branch, all threads
        // return without touching the named barrier.
        if (g == 0) {
            float4 v = *reinterpret_cast<const float4*>(me + (size_t)k * H_ + f);
            *reinterpret_cast<float4*>(op) = v;
        }
        return;
    }

    // defensive clamps: keep all generated row indices inside [0, S) and the
    // span within the 64 covered rows (reference guarantees length < 64, so
    // this never changes the result; it only makes any input safe).
    const int s  = s_raw < S_ ? s_raw : S_;
    int       e  = e_raw < S_ ? e_raw : S_;
    const int em = s + 4 * GROUPS;               // s + 64
    e = e < em ? e : em;

    const float* base = hs + ((size_t)b * S_) * H_ + f;

    const float4 NEG = make_float4(-FLT_MAX, -FLT_MAX, -FLT_MAX, -FLT_MAX);

    // rows covered: s+g+16j, j in [0,4) => s..s+63. 4 independent PREDICATED
    // loads per thread (no duplicate traffic), back-to-back: one latency wait.
    const int r0 = s + g;
    const int r1 = r0 + GROUPS;
    const int r2 = r0 + 2 * GROUPS;
    const int r3 = r0 + 3 * GROUPS;

    float4 a0 = (r0 < e) ? *reinterpret_cast<const float4*>(base + (size_t)r0 * H_) : NEG;
    float4 a1 = (r1 < e) ? *reinterpret_cast<const float4*>(base + (size_t)r1 * H_) : NEG;
    float4 a2 = (r2 < e) ? *reinterpret_cast<const float4*>(base + (size_t)r2 * H_) : NEG;
    float4 a3 = (r3 < e) ? *reinterpret_cast<const float4*>(base + (size_t)r3 * H_) : NEG;

    part[g][lane] = f4max(f4max(a0, a1), f4max(a2, a3));

    // Asymmetric barrier: warps 1..15 arrive and EXIT immediately (SM frees
    // them right after their loads land); only warp 0 blocks, reduces, stores.
    if (g != 0) {
        asm volatile("bar.arrive 1, %0;" :: "r"(THREADS) : "memory");
        return;
    }
    asm volatile("bar.sync 1, %0;" :: "r"(THREADS) : "memory");

    // 15 independent LDS.128 + fmax tree (single warp)
    float4 acc = part[0][lane];
    #pragma unroll
    for (int i = 1; i < GROUPS; i++)
        acc = f4max(acc, part[i][lane]);
    *reinterpret_cast<float4*>(op) = acc;
}

extern "C" void kernel_launch(void* const* d_in, const int* in_sizes, int n_in,
                              void* d_out, int out_size) {
    const float* hs  = (const float*)d_in[0];
    const int*   st  = (const int*)d_in[1];
    const int*   en  = (const int*)d_in[2];
    const float* me  = (const float*)d_in[3];
    float*       out = (float*)d_out;

    dim3 grid(B_ * K_ * CHUNKS);   // 512 blocks x 512 threads
    span_max_kernel<<<grid, THREADS>>>(hs, st, en, me, out);
}